// round 7
// baseline (speedup 1.0000x reference)
#include <cuda_runtime.h>
#include <cuda_bf16.h>
#include <cstdint>
#include <math.h>

#define N_NODES 50000
#define N_EDGES 640000
#define F 128
#define F4 32            // F/4
#define NCLASS 40
#define SCAN_BLKS 49     // 49*1024 = 50176 >= N_NODES

// ---------------- scratch (static __device__, no allocation) ----------------
__device__ float4 g_h [N_NODES * F4];   // GEMM output (h = x @ W)
__device__ float4 g_xa[N_NODES * F4];   // activations ping
__device__ float4 g_xb[N_NODES * F4];   // activations pong
__device__ int    g_cnt[N_NODES];
__device__ int    g_off[N_NODES + 1];
__device__ int    g_cur[N_NODES];
__device__ int    g_srcs[N_EDGES];
__device__ int    g_bsum[64];
__device__ int    g_bpre[64];

// ---------------- CSR build ----------------
__global__ void zero_cnt_kernel() {
    int i = blockIdx.x * blockDim.x + threadIdx.x;
    if (i < N_NODES) g_cnt[i] = 0;
}

__global__ void hist_kernel(const int* __restrict__ dst) {
    int e = blockIdx.x * blockDim.x + threadIdx.x;
    if (e < N_EDGES) atomicAdd(&g_cnt[dst[e]], 1);
}

__global__ void scanA_kernel() {
    __shared__ int sh[1024];
    int tid = threadIdx.x;
    int i = blockIdx.x * 1024 + tid;
    int v = (i < N_NODES) ? g_cnt[i] : 0;
    sh[tid] = v;
    __syncthreads();
    for (int off = 1; off < 1024; off <<= 1) {
        int t = (tid >= off) ? sh[tid - off] : 0;
        __syncthreads();
        sh[tid] += t;
        __syncthreads();
    }
    if (i < N_NODES) g_off[i] = sh[tid] - v;
    if (tid == 1023) g_bsum[blockIdx.x] = sh[1023];
}

__global__ void scanB_kernel() {
    __shared__ int sh[64];
    int tid = threadIdx.x;
    int v = (tid < SCAN_BLKS) ? g_bsum[tid] : 0;
    sh[tid] = v;
    __syncthreads();
    for (int off = 1; off < 64; off <<= 1) {
        int t = (tid >= off) ? sh[tid - off] : 0;
        __syncthreads();
        sh[tid] += t;
        __syncthreads();
    }
    if (tid < SCAN_BLKS) g_bpre[tid] = sh[tid] - v;
    if (tid == 63) g_off[N_NODES] = sh[63];
}

__global__ void scanC_kernel() {
    int i = blockIdx.x * 1024 + threadIdx.x;
    if (i < N_NODES) {
        int o = g_off[i] + g_bpre[blockIdx.x];
        g_off[i] = o;
        g_cur[i] = o;
    }
}

__global__ void fill_kernel(const int* __restrict__ src,
                            const int* __restrict__ dst) {
    int e = blockIdx.x * blockDim.x + threadIdx.x;
    if (e < N_EDGES) {
        int d = dst[e];
        int p = atomicAdd(&g_cur[d], 1);
        g_srcs[p] = src[e];
    }
}

// ---------------- tensor-core GEMM (bf16 split, 3x mma) ----------------
// g_h[n,128] = IN[n,128] @ W[128,128], fp32-equivalent via hi/lo bf16 split.
// 128 rows x 128 cols per block, 8 warps, warp tile = 32 rows x 64 cols.
#define PA 24    // X slab pitch in bf16 (16 data + 8 pad), 48B rows
#define PB 136   // Wt pitch in bf16 (128 data + 8 pad), 272B rows
#define GEMM_SMEM ((128 * PB * 2 + 128 * PA * 2) * 2)   // 81920 B

#define LDSM_X4(r0,r1,r2,r3,addr) \
    asm volatile("ldmatrix.sync.aligned.m8n8.x4.shared.b16 {%0,%1,%2,%3}, [%4];" \
        : "=r"(r0),"=r"(r1),"=r"(r2),"=r"(r3) : "r"(addr))
#define LDSM_X2(r0,r1,addr) \
    asm volatile("ldmatrix.sync.aligned.m8n8.x2.shared.b16 {%0,%1}, [%2];" \
        : "=r"(r0),"=r"(r1) : "r"(addr))
#define MMA16816(d,a0,a1,a2,a3,b0,b1) \
    asm volatile("mma.sync.aligned.m16n8k16.row.col.f32.bf16.bf16.f32 " \
        "{%0,%1,%2,%3},{%4,%5,%6,%7},{%8,%9},{%0,%1,%2,%3};" \
        : "+f"(d[0]),"+f"(d[1]),"+f"(d[2]),"+f"(d[3]) \
        : "r"(a0),"r"(a1),"r"(a2),"r"(a3),"r"(b0),"r"(b1))

__device__ __forceinline__ unsigned int smem_u32(const void* p) {
    return (unsigned int)__cvta_generic_to_shared(p);
}

template<int SEL>
__global__ __launch_bounds__(256, 2)
void gemm_mma_kernel(const float4* __restrict__ Xext,
                     const float* __restrict__ W, int nrows) {
    extern __shared__ __nv_bfloat16 sm_b[];
    __nv_bfloat16* wthi = sm_b;                   // [128 n][PB k]
    __nv_bfloat16* wtlo = wthi + 128 * PB;
    __nv_bfloat16* xhi  = wtlo + 128 * PB;        // [128 r][PA k-slab]
    __nv_bfloat16* xlo  = xhi  + 128 * PA;

    const int tid  = threadIdx.x;
    const int lane = tid & 31;
    const int w    = tid >> 5;
    const int wr   = (w & 3) * 32;     // warp row offset
    const int wc   = (w >> 2) * 64;    // warp col offset
    const int row0 = blockIdx.x * 128;

    // W[k][n] -> transposed hi/lo bf16 wt[n][k]
    for (int i = tid; i < 128 * 32; i += 256) {
        int k = i >> 5, c4 = i & 31;
        float4 wv = ((const float4*)W)[k * 32 + c4];
        float vals[4] = {wv.x, wv.y, wv.z, wv.w};
        #pragma unroll
        for (int j = 0; j < 4; j++) {
            int n = c4 * 4 + j;
            __nv_bfloat16 h = __float2bfloat16(vals[j]);
            wthi[n * PB + k] = h;
            wtlo[n * PB + k] = __float2bfloat16(vals[j] - __bfloat162float(h));
        }
    }

    float acc[2][8][4];
    #pragma unroll
    for (int mt = 0; mt < 2; mt++)
        #pragma unroll
        for (int nt = 0; nt < 8; nt++)
            #pragma unroll
            for (int j = 0; j < 4; j++) acc[mt][nt][j] = 0.f;

    const int l15 = lane & 15;
    const int koA = (lane >> 4) << 3;          // 0 / 8 for A x4
    const int koB = (l15 >> 3) << 3;           // 0 / 8 for B x2
    const int nB0 = wc + (l15 & 7);

    for (int ks = 0; ks < 8; ks++) {
        // load + split X slab: 128 rows x 16 k
        for (int i = tid; i < 512; i += 256) {
            int r = i >> 2, c4 = i & 3;
            int gr = row0 + r;
            float4 v = make_float4(0.f, 0.f, 0.f, 0.f);
            if (gr < nrows) {
                if (SEL == 0)      v = Xext[gr * F4 + ks * 4 + c4];
                else if (SEL == 1) v = g_xa[gr * F4 + ks * 4 + c4];
                else               v = g_xb[gr * F4 + ks * 4 + c4];
            }
            float vals[4] = {v.x, v.y, v.z, v.w};
            int base = r * PA + c4 * 4;
            #pragma unroll
            for (int j = 0; j < 4; j++) {
                __nv_bfloat16 h = __float2bfloat16(vals[j]);
                xhi[base + j] = h;
                xlo[base + j] = __float2bfloat16(vals[j] - __bfloat162float(h));
            }
        }
        __syncthreads();

        unsigned int ahi[2][4], alo[2][4];
        #pragma unroll
        for (int mt = 0; mt < 2; mt++) {
            int r = wr + mt * 16 + l15;
            LDSM_X4(ahi[mt][0], ahi[mt][1], ahi[mt][2], ahi[mt][3],
                    smem_u32(xhi + r * PA + koA));
            LDSM_X4(alo[mt][0], alo[mt][1], alo[mt][2], alo[mt][3],
                    smem_u32(xlo + r * PA + koA));
        }
        #pragma unroll
        for (int nt = 0; nt < 8; nt++) {
            int boff = (nB0 + nt * 8) * PB + ks * 16 + koB;
            unsigned int bh0, bh1, bl0, bl1;
            LDSM_X2(bh0, bh1, smem_u32(wthi + boff));
            LDSM_X2(bl0, bl1, smem_u32(wtlo + boff));
            #pragma unroll
            for (int mt = 0; mt < 2; mt++) {
                MMA16816(acc[mt][nt], ahi[mt][0], ahi[mt][1], ahi[mt][2], ahi[mt][3], bh0, bh1);
                MMA16816(acc[mt][nt], ahi[mt][0], ahi[mt][1], ahi[mt][2], ahi[mt][3], bl0, bl1);
                MMA16816(acc[mt][nt], alo[mt][0], alo[mt][1], alo[mt][2], alo[mt][3], bh0, bh1);
            }
        }
        __syncthreads();
    }

    // store accumulators (fragment: lane t -> r=t/4 (+8), n=(t%4)*2 (+1))
    float2* H2 = (float2*)g_h;
    int rA = lane >> 2;
    int cB = (lane & 3) * 2;
    #pragma unroll
    for (int mt = 0; mt < 2; mt++) {
        #pragma unroll
        for (int nt = 0; nt < 8; nt++) {
            int col2 = (wc + nt * 8 + cB) >> 1;
            int gr = row0 + wr + mt * 16 + rA;
            if (gr < nrows)
                H2[gr * 64 + col2] = make_float2(acc[mt][nt][0], acc[mt][nt][1]);
            if (gr + 8 < nrows)
                H2[(gr + 8) * 64 + col2] = make_float2(acc[mt][nt][2], acc[mt][nt][3]);
        }
    }
}

// ---------------- aggregate + bias + L2 normalize + ReLU ----------------
template<int SEL>
__global__ void agg_norm_relu_kernel(const float* __restrict__ bias,
                                     float4* __restrict__ OUText) {
    int node = (blockIdx.x * blockDim.x + threadIdx.x) >> 5;
    int lane = threadIdx.x & 31;
    if (node >= N_NODES) return;
    int s = g_off[node], e = g_off[node + 1];
    float4 acc = make_float4(0.f, 0.f, 0.f, 0.f);
    int i = s;
    for (; i + 3 < e; i += 4) {
        int u0 = g_srcs[i + 0];
        int u1 = g_srcs[i + 1];
        int u2 = g_srcs[i + 2];
        int u3 = g_srcs[i + 3];
        float4 v0 = g_h[u0 * F4 + lane];
        float4 v1 = g_h[u1 * F4 + lane];
        float4 v2 = g_h[u2 * F4 + lane];
        float4 v3 = g_h[u3 * F4 + lane];
        acc.x += v0.x + v1.x + v2.x + v3.x;
        acc.y += v0.y + v1.y + v2.y + v3.y;
        acc.z += v0.z + v1.z + v2.z + v3.z;
        acc.w += v0.w + v1.w + v2.w + v3.w;
    }
    for (; i < e; i++) {
        int u = g_srcs[i];
        float4 v = g_h[u * F4 + lane];
        acc.x += v.x; acc.y += v.y; acc.z += v.z; acc.w += v.w;
    }
    float4 b4 = ((const float4*)bias)[lane];
    acc.x += b4.x; acc.y += b4.y; acc.z += b4.z; acc.w += b4.w;
    float ss = acc.x * acc.x + acc.y * acc.y + acc.z * acc.z + acc.w * acc.w;
    #pragma unroll
    for (int off = 16; off > 0; off >>= 1)
        ss += __shfl_xor_sync(0xFFFFFFFFu, ss, off);
    float inv = 1.f / fmaxf(sqrtf(ss), 1e-12f);
    float4 r;
    r.x = fmaxf(acc.x * inv, 0.f);
    r.y = fmaxf(acc.y * inv, 0.f);
    r.z = fmaxf(acc.z * inv, 0.f);
    r.w = fmaxf(acc.w * inv, 0.f);
    if (SEL == 0)      OUText[node * F4 + lane] = r;
    else if (SEL == 1) g_xa[node * F4 + lane]   = r;
    else               g_xb[node * F4 + lane]   = r;
}

// ---------------- final linear + softmax ----------------
__global__ void final_kernel(const float* __restrict__ X4,
                             const float* __restrict__ Wl,
                             const float* __restrict__ bl,
                             float* __restrict__ logits,
                             float* __restrict__ probs) {
    __shared__ float xsh[32][129];
    __shared__ float wsh[F][NCLASS];
    __shared__ float lsh[32][NCLASS];
    __shared__ float mx[32], inv[32];
    int tid = threadIdx.x;
    int n0 = blockIdx.x * 32;

    for (int i = tid; i < 32 * F; i += 256) {
        int n = i >> 7, k = i & 127;
        int gn = n0 + n;
        xsh[n][k] = (gn < N_NODES) ? X4[gn * F + k] : 0.f;
    }
    for (int i = tid; i < F * NCLASS; i += 256)
        wsh[i / NCLASS][i % NCLASS] = Wl[i];
    __syncthreads();

    for (int idx = tid; idx < 32 * NCLASS; idx += 256) {
        int n = idx / NCLASS, c = idx % NCLASS;
        float s = bl[c];
        #pragma unroll
        for (int k = 0; k < F; k++) s += xsh[n][k] * wsh[k][c];
        lsh[n][c] = s;
    }
    __syncthreads();

    if (tid < 32) {
        float m = -1e30f;
        #pragma unroll
        for (int c = 0; c < NCLASS; c++) m = fmaxf(m, lsh[tid][c]);
        float sum = 0.f;
        #pragma unroll
        for (int c = 0; c < NCLASS; c++) sum += expf(lsh[tid][c] - m);
        mx[tid] = m; inv[tid] = 1.f / sum;
    }
    __syncthreads();

    for (int idx = tid; idx < 32 * NCLASS; idx += 256) {
        int n = idx / NCLASS, c = idx % NCLASS;
        int gn = n0 + n;
        if (gn < N_NODES) {
            float l = lsh[n][c];
            logits[gn * NCLASS + c] = l;
            probs[gn * NCLASS + c]  = expf(l - mx[n]) * inv[n];
        }
    }
}

// ---------------- launch ----------------
extern "C" void kernel_launch(void* const* d_in, const int* in_sizes, int n_in,
                              void* d_out, int out_size) {
    const float* x  = (const float*)d_in[0];
    const int*   ei = (const int*)d_in[1];   // int32 (2, 640000)
    const float* W1 = (const float*)d_in[2];
    const float* b1 = (const float*)d_in[3];
    const float* W2 = (const float*)d_in[4];
    const float* b2 = (const float*)d_in[5];
    const float* W3 = (const float*)d_in[6];
    const float* b3 = (const float*)d_in[7];
    const float* W4 = (const float*)d_in[8];
    const float* b4 = (const float*)d_in[9];
    const float* Wl = (const float*)d_in[10];
    const float* bl = (const float*)d_in[11];

    const int* src = ei;
    const int* dst = ei + N_EDGES;

    float* out    = (float*)d_out;
    float* logits = out;
    float* probs  = out + N_NODES * NCLASS;
    float* x4out  = out + 2 * N_NODES * NCLASS;

    const int T = 256;
    const int gemm_blocks = (N_NODES + 127) / 128;          // 391
    const int agg_blocks  = (N_NODES * 32 + T - 1) / T;     // 6250
    const int edge_blocks = (N_EDGES + T - 1) / T;          // 2500

    cudaFuncSetAttribute(gemm_mma_kernel<0>, cudaFuncAttributeMaxDynamicSharedMemorySize, GEMM_SMEM);
    cudaFuncSetAttribute(gemm_mma_kernel<1>, cudaFuncAttributeMaxDynamicSharedMemorySize, GEMM_SMEM);
    cudaFuncSetAttribute(gemm_mma_kernel<2>, cudaFuncAttributeMaxDynamicSharedMemorySize, GEMM_SMEM);

    // Build CSR once per call
    zero_cnt_kernel<<<(N_NODES + T - 1) / T, T>>>();
    hist_kernel<<<edge_blocks, T>>>(dst);
    scanA_kernel<<<SCAN_BLKS, 1024>>>();
    scanB_kernel<<<1, 64>>>();
    scanC_kernel<<<SCAN_BLKS, 1024>>>();
    fill_kernel<<<edge_blocks, T>>>(src, dst);

    // layer 1: x -> g_h -> g_xa
    gemm_mma_kernel<0><<<gemm_blocks, T, GEMM_SMEM>>>((const float4*)x, W1, N_NODES);
    agg_norm_relu_kernel<1><<<agg_blocks, T>>>(b1, nullptr);
    // layer 2: g_xa -> g_h -> g_xb
    gemm_mma_kernel<1><<<gemm_blocks, T, GEMM_SMEM>>>(nullptr, W2, N_NODES);
    agg_norm_relu_kernel<2><<<agg_blocks, T>>>(b2, nullptr);
    // layer 3: g_xb -> g_h -> g_xa
    gemm_mma_kernel<2><<<gemm_blocks, T, GEMM_SMEM>>>(nullptr, W3, N_NODES);
    agg_norm_relu_kernel<1><<<agg_blocks, T>>>(b3, nullptr);
    // layer 4: g_xa -> g_h -> x4out
    gemm_mma_kernel<1><<<gemm_blocks, T, GEMM_SMEM>>>(nullptr, W4, N_NODES);
    agg_norm_relu_kernel<0><<<agg_blocks, T>>>(b4, (float4*)x4out);

    // head: logits + softmax
    final_kernel<<<(N_NODES + 31) / 32, T>>>(x4out, Wl, bl, logits, probs);
}

// round 8
// speedup vs baseline: 1.4384x; 1.4384x over previous
#include <cuda_runtime.h>
#include <cuda_bf16.h>
#include <cstdint>
#include <math.h>

#define N_NODES 50000
#define N_EDGES 640000
#define F 128
#define F4 32
#define NCLASS 40
#define SCAN_BLKS 49

// ---------------- scratch (static __device__, no allocation) ----------------
__device__ float4        g_h   [N_NODES * F4];      // GEMM output (fp32)
__device__ __nv_bfloat16 g_xhi [N_NODES * F];       // activation hi
__device__ __nv_bfloat16 g_xlo [N_NODES * F];       // activation lo
__device__ __nv_bfloat16 g_wthi[F * F];             // W^T hi (per layer, overwritten)
__device__ __nv_bfloat16 g_wtlo[F * F];             // W^T lo
__device__ int g_cnt[N_NODES];
__device__ int g_off[N_NODES + 1];
__device__ int g_cur[N_NODES];
__device__ int g_srcs[N_EDGES];
__device__ int g_bsum[64];
__device__ int g_bpre[64];

// ---------------- CSR build ----------------
__global__ void zero_cnt_kernel() {
    int i = blockIdx.x * blockDim.x + threadIdx.x;
    if (i < N_NODES) g_cnt[i] = 0;
}

__global__ void hist_kernel(const int* __restrict__ dst) {
    int e = blockIdx.x * blockDim.x + threadIdx.x;
    if (e < N_EDGES) atomicAdd(&g_cnt[dst[e]], 1);
}

__global__ void scanA_kernel() {
    __shared__ int sh[1024];
    int tid = threadIdx.x;
    int i = blockIdx.x * 1024 + tid;
    int v = (i < N_NODES) ? g_cnt[i] : 0;
    sh[tid] = v;
    __syncthreads();
    for (int off = 1; off < 1024; off <<= 1) {
        int t = (tid >= off) ? sh[tid - off] : 0;
        __syncthreads();
        sh[tid] += t;
        __syncthreads();
    }
    if (i < N_NODES) g_off[i] = sh[tid] - v;
    if (tid == 1023) g_bsum[blockIdx.x] = sh[1023];
}

__global__ void scanB_kernel() {
    __shared__ int sh[64];
    int tid = threadIdx.x;
    int v = (tid < SCAN_BLKS) ? g_bsum[tid] : 0;
    sh[tid] = v;
    __syncthreads();
    for (int off = 1; off < 64; off <<= 1) {
        int t = (tid >= off) ? sh[tid - off] : 0;
        __syncthreads();
        sh[tid] += t;
        __syncthreads();
    }
    if (tid < SCAN_BLKS) g_bpre[tid] = sh[tid] - v;
    if (tid == 63) g_off[N_NODES] = sh[63];
}

__global__ void scanC_kernel() {
    int i = blockIdx.x * 1024 + threadIdx.x;
    if (i < N_NODES) {
        int o = g_off[i] + g_bpre[blockIdx.x];
        g_off[i] = o;
        g_cur[i] = o;
    }
}

__global__ void fill_kernel(const int* __restrict__ src,
                            const int* __restrict__ dst) {
    int e = blockIdx.x * blockDim.x + threadIdx.x;
    if (e < N_EDGES) {
        int d = dst[e];
        int p = atomicAdd(&g_cur[d], 1);
        g_srcs[p] = src[e];
    }
}

// ---------------- per-layer prep: W[k][n] -> Wt hi/lo bf16 [n][k] ----------------
__global__ void wprep_kernel(const float* __restrict__ W) {
    int i = blockIdx.x * blockDim.x + threadIdx.x;   // 16384
    int k = i >> 7, n = i & 127;
    float w = W[k * F + n];
    __nv_bfloat16 h = __float2bfloat16(w);
    g_wthi[n * F + k] = h;
    g_wtlo[n * F + k] = __float2bfloat16(w - __bfloat162float(h));
}

// ---------------- one-time: external x -> hi/lo bf16 ----------------
__global__ void xsplit_kernel(const float4* __restrict__ X) {
    int i = blockIdx.x * blockDim.x + threadIdx.x;   // N_NODES*F4
    if (i >= N_NODES * F4) return;
    float4 v = X[i];
    float vals[4] = {v.x, v.y, v.z, v.w};
    __nv_bfloat16 hi[4], lo[4];
    #pragma unroll
    for (int j = 0; j < 4; j++) {
        hi[j] = __float2bfloat16(vals[j]);
        lo[j] = __float2bfloat16(vals[j] - __bfloat162float(hi[j]));
    }
    *(uint2*)&g_xhi[i * 4] = *(uint2*)hi;
    *(uint2*)&g_xlo[i * 4] = *(uint2*)lo;
}

// ---------------- tensor-core GEMM v3 (pure bf16 loads, 3x mma) ----------------
// g_h[n,128] = Xsplit[n,128] @ W, 128x128 tile/block, 8 warps.
#define PT 40     // smem pitch in bf16 (32 data + 8 pad) = 80B rows
#define GEMM_SMEM (4 * 128 * PT * 2)   // xhi,xlo,whi,wlo slabs: 40960 B

#define LDSM_X4(r0,r1,r2,r3,addr) \
    asm volatile("ldmatrix.sync.aligned.m8n8.x4.shared.b16 {%0,%1,%2,%3}, [%4];" \
        : "=r"(r0),"=r"(r1),"=r"(r2),"=r"(r3) : "r"(addr))
#define LDSM_X2(r0,r1,addr) \
    asm volatile("ldmatrix.sync.aligned.m8n8.x2.shared.b16 {%0,%1}, [%2];" \
        : "=r"(r0),"=r"(r1) : "r"(addr))
#define MMA16816(d,a0,a1,a2,a3,b0,b1) \
    asm volatile("mma.sync.aligned.m16n8k16.row.col.f32.bf16.bf16.f32 " \
        "{%0,%1,%2,%3},{%4,%5,%6,%7},{%8,%9},{%0,%1,%2,%3};" \
        : "+f"(d[0]),"+f"(d[1]),"+f"(d[2]),"+f"(d[3]) \
        : "r"(a0),"r"(a1),"r"(a2),"r"(a3),"r"(b0),"r"(b1))

__device__ __forceinline__ unsigned int smem_u32(const void* p) {
    return (unsigned int)__cvta_generic_to_shared(p);
}

__global__ __launch_bounds__(256, 2)
void gemm_mma_kernel(int nrows) {
    extern __shared__ __nv_bfloat16 sm_b[];
    __nv_bfloat16* xhi_s = sm_b;                 // [128][PT]
    __nv_bfloat16* xlo_s = xhi_s + 128 * PT;
    __nv_bfloat16* whi_s = xlo_s + 128 * PT;     // [128 n][PT k]
    __nv_bfloat16* wlo_s = whi_s + 128 * PT;

    const int tid  = threadIdx.x;
    const int lane = tid & 31;
    const int w    = tid >> 5;
    const int wr   = (w & 3) * 32;
    const int wc   = (w >> 2) * 64;
    const int row0 = blockIdx.x * 128;

    float acc[2][8][4];
    #pragma unroll
    for (int mt = 0; mt < 2; mt++)
        #pragma unroll
        for (int nt = 0; nt < 8; nt++)
            #pragma unroll
            for (int j = 0; j < 4; j++) acc[mt][nt][j] = 0.f;

    const int l15 = lane & 15;
    const int koA = (lane >> 4) << 3;
    const int koB = (l15 >> 3) << 3;
    const uint4 z4 = make_uint4(0u, 0u, 0u, 0u);

    for (int ks = 0; ks < 4; ks++) {
        // load X slab (hi+lo) + W slab (hi+lo): rows x 32 k, uint4 = 8 bf16
        #pragma unroll
        for (int i = tid; i < 2048; i += 256) {
            int which = i >> 9;          // 0:xhi 1:xlo 2:whi 3:wlo
            int r = (i >> 2) & 127;
            int c = i & 3;               // k chunk of 8
            uint4 v = z4;
            int gidx = r * 16 + ks * 4 + c;   // uint4 index into [*][128] bf16 array
            if (which == 0) {
                int gr = row0 + r;
                if (gr < nrows) v = ((const uint4*)g_xhi)[gr * 16 + ks * 4 + c];
            } else if (which == 1) {
                int gr = row0 + r;
                if (gr < nrows) v = ((const uint4*)g_xlo)[gr * 16 + ks * 4 + c];
            } else if (which == 2) {
                v = ((const uint4*)g_wthi)[gidx];
            } else {
                v = ((const uint4*)g_wtlo)[gidx];
            }
            __nv_bfloat16* base =
                (which == 0) ? xhi_s : (which == 1) ? xlo_s :
                (which == 2) ? whi_s : wlo_s;
            *(uint4*)(base + r * PT + c * 8) = v;
        }
        __syncthreads();

        #pragma unroll
        for (int j = 0; j < 2; j++) {          // two k16 steps per slab
            unsigned int ahi[2][4], alo[2][4];
            #pragma unroll
            for (int mt = 0; mt < 2; mt++) {
                int r = wr + mt * 16 + l15;
                LDSM_X4(ahi[mt][0], ahi[mt][1], ahi[mt][2], ahi[mt][3],
                        smem_u32(xhi_s + r * PT + j * 16 + koA));
                LDSM_X4(alo[mt][0], alo[mt][1], alo[mt][2], alo[mt][3],
                        smem_u32(xlo_s + r * PT + j * 16 + koA));
            }
            #pragma unroll
            for (int nt = 0; nt < 8; nt++) {
                int boff = (wc + nt * 8 + (l15 & 7)) * PT + j * 16 + koB;
                unsigned int bh0, bh1, bl0, bl1;
                LDSM_X2(bh0, bh1, smem_u32(whi_s + boff));
                LDSM_X2(bl0, bl1, smem_u32(wlo_s + boff));
                #pragma unroll
                for (int mt = 0; mt < 2; mt++) {
                    MMA16816(acc[mt][nt], ahi[mt][0], ahi[mt][1], ahi[mt][2], ahi[mt][3], bh0, bh1);
                    MMA16816(acc[mt][nt], ahi[mt][0], ahi[mt][1], ahi[mt][2], ahi[mt][3], bl0, bl1);
                    MMA16816(acc[mt][nt], alo[mt][0], alo[mt][1], alo[mt][2], alo[mt][3], bh0, bh1);
                }
            }
        }
        __syncthreads();
    }

    float2* H2 = (float2*)g_h;
    int rA = lane >> 2;
    int cB = (lane & 3) * 2;
    #pragma unroll
    for (int mt = 0; mt < 2; mt++) {
        #pragma unroll
        for (int nt = 0; nt < 8; nt++) {
            int col2 = (wc + nt * 8 + cB) >> 1;
            int gr = row0 + wr + mt * 16 + rA;
            if (gr < nrows)
                H2[gr * 64 + col2] = make_float2(acc[mt][nt][0], acc[mt][nt][1]);
            if (gr + 8 < nrows)
                H2[(gr + 8) * 64 + col2] = make_float2(acc[mt][nt][2], acc[mt][nt][3]);
        }
    }
}

// ---------------- aggregate + bias + L2 normalize + ReLU ----------------
// BF16OUT=1: write hi/lo bf16 activations; BF16OUT=0: write fp32 to OUText.
template<int BF16OUT>
__global__ void agg_norm_relu_kernel(const float* __restrict__ bias,
                                     float4* __restrict__ OUText) {
    int node = (blockIdx.x * blockDim.x + threadIdx.x) >> 5;
    int lane = threadIdx.x & 31;
    if (node >= N_NODES) return;
    int s = g_off[node], e = g_off[node + 1];
    float4 acc = make_float4(0.f, 0.f, 0.f, 0.f);
    int i = s;
    for (; i + 3 < e; i += 4) {
        int u0 = g_srcs[i + 0];
        int u1 = g_srcs[i + 1];
        int u2 = g_srcs[i + 2];
        int u3 = g_srcs[i + 3];
        float4 v0 = g_h[u0 * F4 + lane];
        float4 v1 = g_h[u1 * F4 + lane];
        float4 v2 = g_h[u2 * F4 + lane];
        float4 v3 = g_h[u3 * F4 + lane];
        acc.x += v0.x + v1.x + v2.x + v3.x;
        acc.y += v0.y + v1.y + v2.y + v3.y;
        acc.z += v0.z + v1.z + v2.z + v3.z;
        acc.w += v0.w + v1.w + v2.w + v3.w;
    }
    for (; i < e; i++) {
        int u = g_srcs[i];
        float4 v = g_h[u * F4 + lane];
        acc.x += v.x; acc.y += v.y; acc.z += v.z; acc.w += v.w;
    }
    float4 b4 = ((const float4*)bias)[lane];
    acc.x += b4.x; acc.y += b4.y; acc.z += b4.z; acc.w += b4.w;
    float ss = acc.x * acc.x + acc.y * acc.y + acc.z * acc.z + acc.w * acc.w;
    #pragma unroll
    for (int off = 16; off > 0; off >>= 1)
        ss += __shfl_xor_sync(0xFFFFFFFFu, ss, off);
    float inv = 1.f / fmaxf(sqrtf(ss), 1e-12f);
    float vals[4];
    vals[0] = fmaxf(acc.x * inv, 0.f);
    vals[1] = fmaxf(acc.y * inv, 0.f);
    vals[2] = fmaxf(acc.z * inv, 0.f);
    vals[3] = fmaxf(acc.w * inv, 0.f);
    if (BF16OUT) {
        __nv_bfloat16 hi[4], lo[4];
        #pragma unroll
        for (int j = 0; j < 4; j++) {
            hi[j] = __float2bfloat16(vals[j]);
            lo[j] = __float2bfloat16(vals[j] - __bfloat162float(hi[j]));
        }
        int idx = node * F + lane * 4;
        *(uint2*)&g_xhi[idx] = *(uint2*)hi;
        *(uint2*)&g_xlo[idx] = *(uint2*)lo;
    } else {
        OUText[node * F4 + lane] = make_float4(vals[0], vals[1], vals[2], vals[3]);
    }
}

// ---------------- final linear + softmax ----------------
__global__ void final_kernel(const float* __restrict__ X4,
                             const float* __restrict__ Wl,
                             const float* __restrict__ bl,
                             float* __restrict__ logits,
                             float* __restrict__ probs) {
    __shared__ float xsh[32][129];
    __shared__ float wsh[F][NCLASS];
    __shared__ float lsh[32][NCLASS];
    __shared__ float mx[32], inv[32];
    int tid = threadIdx.x;
    int n0 = blockIdx.x * 32;

    for (int i = tid; i < 32 * F; i += 256) {
        int n = i >> 7, k = i & 127;
        int gn = n0 + n;
        xsh[n][k] = (gn < N_NODES) ? X4[gn * F + k] : 0.f;
    }
    for (int i = tid; i < F * NCLASS; i += 256)
        wsh[i / NCLASS][i % NCLASS] = Wl[i];
    __syncthreads();

    for (int idx = tid; idx < 32 * NCLASS; idx += 256) {
        int n = idx / NCLASS, c = idx % NCLASS;
        float s = bl[c];
        #pragma unroll
        for (int k = 0; k < F; k++) s += xsh[n][k] * wsh[k][c];
        lsh[n][c] = s;
    }
    __syncthreads();

    if (tid < 32) {
        float m = -1e30f;
        #pragma unroll
        for (int c = 0; c < NCLASS; c++) m = fmaxf(m, lsh[tid][c]);
        float sum = 0.f;
        #pragma unroll
        for (int c = 0; c < NCLASS; c++) sum += expf(lsh[tid][c] - m);
        mx[tid] = m; inv[tid] = 1.f / sum;
    }
    __syncthreads();

    for (int idx = tid; idx < 32 * NCLASS; idx += 256) {
        int n = idx / NCLASS, c = idx % NCLASS;
        int gn = n0 + n;
        if (gn < N_NODES) {
            float l = lsh[n][c];
            logits[gn * NCLASS + c] = l;
            probs[gn * NCLASS + c]  = expf(l - mx[n]) * inv[n];
        }
    }
}

// ---------------- launch ----------------
extern "C" void kernel_launch(void* const* d_in, const int* in_sizes, int n_in,
                              void* d_out, int out_size) {
    const float* x  = (const float*)d_in[0];
    const int*   ei = (const int*)d_in[1];
    const float* W1 = (const float*)d_in[2];
    const float* b1 = (const float*)d_in[3];
    const float* W2 = (const float*)d_in[4];
    const float* b2 = (const float*)d_in[5];
    const float* W3 = (const float*)d_in[6];
    const float* b3 = (const float*)d_in[7];
    const float* W4 = (const float*)d_in[8];
    const float* b4 = (const float*)d_in[9];
    const float* Wl = (const float*)d_in[10];
    const float* bl = (const float*)d_in[11];

    const int* src = ei;
    const int* dst = ei + N_EDGES;

    float* out    = (float*)d_out;
    float* logits = out;
    float* probs  = out + N_NODES * NCLASS;
    float* x4out  = out + 2 * N_NODES * NCLASS;

    const int T = 256;
    const int gemm_blocks = (N_NODES + 127) / 128;       // 391
    const int agg_blocks  = (N_NODES * 32 + T - 1) / T;  // 6250
    const int edge_blocks = (N_EDGES + T - 1) / T;       // 2500

    cudaFuncSetAttribute(gemm_mma_kernel, cudaFuncAttributeMaxDynamicSharedMemorySize, GEMM_SMEM);

    // CSR build (once per call)
    zero_cnt_kernel<<<(N_NODES + T - 1) / T, T>>>();
    hist_kernel<<<edge_blocks, T>>>(dst);
    scanA_kernel<<<SCAN_BLKS, 1024>>>();
    scanB_kernel<<<1, 64>>>();
    scanC_kernel<<<SCAN_BLKS, 1024>>>();
    fill_kernel<<<edge_blocks, T>>>(src, dst);

    // split external x once
    xsplit_kernel<<<(N_NODES * F4 + T - 1) / T, T>>>((const float4*)x);

    // layer 1
    wprep_kernel<<<64, T>>>(W1);
    gemm_mma_kernel<<<gemm_blocks, T, GEMM_SMEM>>>(N_NODES);
    agg_norm_relu_kernel<1><<<agg_blocks, T>>>(b1, nullptr);
    // layer 2
    wprep_kernel<<<64, T>>>(W2);
    gemm_mma_kernel<<<gemm_blocks, T, GEMM_SMEM>>>(N_NODES);
    agg_norm_relu_kernel<1><<<agg_blocks, T>>>(b2, nullptr);
    // layer 3
    wprep_kernel<<<64, T>>>(W3);
    gemm_mma_kernel<<<gemm_blocks, T, GEMM_SMEM>>>(N_NODES);
    agg_norm_relu_kernel<1><<<agg_blocks, T>>>(b3, nullptr);
    // layer 4 -> fp32 straight to d_out
    wprep_kernel<<<64, T>>>(W4);
    gemm_mma_kernel<<<gemm_blocks, T, GEMM_SMEM>>>(N_NODES);
    agg_norm_relu_kernel<0><<<agg_blocks, T>>>(b4, (float4*)x4out);

    // head
    final_kernel<<<(N_NODES + 31) / 32, T>>>(x4out, Wl, bl, logits, probs);
}

// round 9
// speedup vs baseline: 1.6739x; 1.1637x over previous
#include <cuda_runtime.h>
#include <cuda_bf16.h>
#include <cstdint>
#include <math.h>

#define N_NODES 50000
#define N_EDGES 640000
#define F 128
#define F4 32
#define NCLASS 40
#define SCAN_BLKS 49

// ---------------- scratch (static __device__, no allocation) ----------------
__device__ float4        g_h   [N_NODES * F4];      // GEMM output (fp32)
__device__ __nv_bfloat16 g_xhi [N_NODES * F];       // activation hi
__device__ __nv_bfloat16 g_xlo [N_NODES * F];       // activation lo
__device__ __nv_bfloat16 g_wthi[4 * F * F];         // W^T hi, all 4 layers
__device__ __nv_bfloat16 g_wtlo[4 * F * F];         // W^T lo
__device__ int g_cnt[N_NODES];
__device__ int g_off[N_NODES + 1];
__device__ int g_cur[N_NODES];
__device__ int g_srcs[N_EDGES];
__device__ int g_bsum[64];
__device__ int g_bpre[64];

// ---------------- CSR build ----------------
__global__ void zero_cnt_kernel() {
    int i = blockIdx.x * blockDim.x + threadIdx.x;
    if (i < N_NODES) g_cnt[i] = 0;
}

__global__ void hist_kernel(const int* __restrict__ dst) {
    int e = blockIdx.x * blockDim.x + threadIdx.x;
    if (e < N_EDGES) atomicAdd(&g_cnt[dst[e]], 1);
}

__global__ void scanA_kernel() {
    __shared__ int sh[1024];
    int tid = threadIdx.x;
    int i = blockIdx.x * 1024 + tid;
    int v = (i < N_NODES) ? g_cnt[i] : 0;
    sh[tid] = v;
    __syncthreads();
    for (int off = 1; off < 1024; off <<= 1) {
        int t = (tid >= off) ? sh[tid - off] : 0;
        __syncthreads();
        sh[tid] += t;
        __syncthreads();
    }
    if (i < N_NODES) g_off[i] = sh[tid] - v;
    if (tid == 1023) g_bsum[blockIdx.x] = sh[1023];
}

__global__ void scanB_kernel() {
    __shared__ int sh[64];
    int tid = threadIdx.x;
    int v = (tid < SCAN_BLKS) ? g_bsum[tid] : 0;
    sh[tid] = v;
    __syncthreads();
    for (int off = 1; off < 64; off <<= 1) {
        int t = (tid >= off) ? sh[tid - off] : 0;
        __syncthreads();
        sh[tid] += t;
        __syncthreads();
    }
    if (tid < SCAN_BLKS) g_bpre[tid] = sh[tid] - v;
    if (tid == 63) g_off[N_NODES] = sh[63];
}

__global__ void scanC_kernel() {
    int i = blockIdx.x * 1024 + threadIdx.x;
    if (i < N_NODES) {
        int o = g_off[i] + g_bpre[blockIdx.x];
        g_off[i] = o;
        g_cur[i] = o;
    }
}

__global__ void fill_kernel(const int* __restrict__ src,
                            const int* __restrict__ dst) {
    int e = blockIdx.x * blockDim.x + threadIdx.x;
    if (e < N_EDGES) {
        int d = dst[e];
        int p = atomicAdd(&g_cur[d], 1);
        g_srcs[p] = src[e];
    }
}

// ---------------- prep: all 4 layers' W[k][n] -> Wt hi/lo bf16 [n][k] ----------------
__global__ void wprep_all_kernel(const float* __restrict__ W1,
                                 const float* __restrict__ W2,
                                 const float* __restrict__ W3,
                                 const float* __restrict__ W4) {
    int i = blockIdx.x * blockDim.x + threadIdx.x;   // 4*16384
    if (i >= 4 * F * F) return;
    int layer = i >> 14;
    int r = i & (F * F - 1);
    int k = r >> 7, n = r & 127;
    const float* W = (layer == 0) ? W1 : (layer == 1) ? W2 : (layer == 2) ? W3 : W4;
    float w = W[k * F + n];
    __nv_bfloat16 h = __float2bfloat16(w);
    g_wthi[layer * F * F + n * F + k] = h;
    g_wtlo[layer * F * F + n * F + k] = __float2bfloat16(w - __bfloat162float(h));
}

// ---------------- one-time: external x -> hi/lo bf16 ----------------
__global__ void xsplit_kernel(const float4* __restrict__ X) {
    int i = blockIdx.x * blockDim.x + threadIdx.x;
    if (i >= N_NODES * F4) return;
    float4 v = X[i];
    float vals[4] = {v.x, v.y, v.z, v.w};
    __nv_bfloat16 hi[4], lo[4];
    #pragma unroll
    for (int j = 0; j < 4; j++) {
        hi[j] = __float2bfloat16(vals[j]);
        lo[j] = __float2bfloat16(vals[j] - __bfloat162float(hi[j]));
    }
    *(uint2*)&g_xhi[i * 4] = *(uint2*)hi;
    *(uint2*)&g_xlo[i * 4] = *(uint2*)lo;
}

// ---------------- tensor-core GEMM (pure bf16 loads, 3x mma) ----------------
#define PT 40
#define GEMM_SMEM (4 * 128 * PT * 2)   // 40960 B

#define LDSM_X4(r0,r1,r2,r3,addr) \
    asm volatile("ldmatrix.sync.aligned.m8n8.x4.shared.b16 {%0,%1,%2,%3}, [%4];" \
        : "=r"(r0),"=r"(r1),"=r"(r2),"=r"(r3) : "r"(addr))
#define LDSM_X2(r0,r1,addr) \
    asm volatile("ldmatrix.sync.aligned.m8n8.x2.shared.b16 {%0,%1}, [%2];" \
        : "=r"(r0),"=r"(r1) : "r"(addr))
#define MMA16816(d,a0,a1,a2,a3,b0,b1) \
    asm volatile("mma.sync.aligned.m16n8k16.row.col.f32.bf16.bf16.f32 " \
        "{%0,%1,%2,%3},{%4,%5,%6,%7},{%8,%9},{%0,%1,%2,%3};" \
        : "+f"(d[0]),"+f"(d[1]),"+f"(d[2]),"+f"(d[3]) \
        : "r"(a0),"r"(a1),"r"(a2),"r"(a3),"r"(b0),"r"(b1))

__device__ __forceinline__ unsigned int smem_u32(const void* p) {
    return (unsigned int)__cvta_generic_to_shared(p);
}

__global__ __launch_bounds__(256, 2)
void gemm_mma_kernel(int layer, int nrows) {
    extern __shared__ __nv_bfloat16 sm_b[];
    __nv_bfloat16* xhi_s = sm_b;
    __nv_bfloat16* xlo_s = xhi_s + 128 * PT;
    __nv_bfloat16* whi_s = xlo_s + 128 * PT;
    __nv_bfloat16* wlo_s = whi_s + 128 * PT;

    const int tid  = threadIdx.x;
    const int lane = tid & 31;
    const int w    = tid >> 5;
    const int wr   = (w & 3) * 32;
    const int wc   = (w >> 2) * 64;
    const int row0 = blockIdx.x * 128;
    const int woff = layer * (F * F / 8);   // uint4 offset

    float acc[2][8][4];
    #pragma unroll
    for (int mt = 0; mt < 2; mt++)
        #pragma unroll
        for (int nt = 0; nt < 8; nt++)
            #pragma unroll
            for (int j = 0; j < 4; j++) acc[mt][nt][j] = 0.f;

    const int l15 = lane & 15;
    const int koA = (lane >> 4) << 3;
    const int koB = (l15 >> 3) << 3;
    const uint4 z4 = make_uint4(0u, 0u, 0u, 0u);

    for (int ks = 0; ks < 4; ks++) {
        #pragma unroll
        for (int i = tid; i < 2048; i += 256) {
            int which = i >> 9;
            int r = (i >> 2) & 127;
            int c = i & 3;
            uint4 v = z4;
            int gidx = r * 16 + ks * 4 + c;
            if (which == 0) {
                int gr = row0 + r;
                if (gr < nrows) v = ((const uint4*)g_xhi)[gr * 16 + ks * 4 + c];
            } else if (which == 1) {
                int gr = row0 + r;
                if (gr < nrows) v = ((const uint4*)g_xlo)[gr * 16 + ks * 4 + c];
            } else if (which == 2) {
                v = ((const uint4*)g_wthi)[woff + gidx];
            } else {
                v = ((const uint4*)g_wtlo)[woff + gidx];
            }
            __nv_bfloat16* base =
                (which == 0) ? xhi_s : (which == 1) ? xlo_s :
                (which == 2) ? whi_s : wlo_s;
            *(uint4*)(base + r * PT + c * 8) = v;
        }
        __syncthreads();

        #pragma unroll
        for (int j = 0; j < 2; j++) {
            unsigned int ahi[2][4], alo[2][4];
            #pragma unroll
            for (int mt = 0; mt < 2; mt++) {
                int r = wr + mt * 16 + l15;
                LDSM_X4(ahi[mt][0], ahi[mt][1], ahi[mt][2], ahi[mt][3],
                        smem_u32(xhi_s + r * PT + j * 16 + koA));
                LDSM_X4(alo[mt][0], alo[mt][1], alo[mt][2], alo[mt][3],
                        smem_u32(xlo_s + r * PT + j * 16 + koA));
            }
            #pragma unroll
            for (int nt = 0; nt < 8; nt++) {
                int boff = (wc + nt * 8 + (l15 & 7)) * PT + j * 16 + koB;
                unsigned int bh0, bh1, bl0, bl1;
                LDSM_X2(bh0, bh1, smem_u32(whi_s + boff));
                LDSM_X2(bl0, bl1, smem_u32(wlo_s + boff));
                #pragma unroll
                for (int mt = 0; mt < 2; mt++) {
                    MMA16816(acc[mt][nt], ahi[mt][0], ahi[mt][1], ahi[mt][2], ahi[mt][3], bh0, bh1);
                    MMA16816(acc[mt][nt], ahi[mt][0], ahi[mt][1], ahi[mt][2], ahi[mt][3], bl0, bl1);
                    MMA16816(acc[mt][nt], alo[mt][0], alo[mt][1], alo[mt][2], alo[mt][3], bh0, bh1);
                }
            }
        }
        __syncthreads();
    }

    float2* H2 = (float2*)g_h;
    int rA = lane >> 2;
    int cB = (lane & 3) * 2;
    #pragma unroll
    for (int mt = 0; mt < 2; mt++) {
        #pragma unroll
        for (int nt = 0; nt < 8; nt++) {
            int col2 = (wc + nt * 8 + cB) >> 1;
            int gr = row0 + wr + mt * 16 + rA;
            if (gr < nrows)
                H2[gr * 64 + col2] = make_float2(acc[mt][nt][0], acc[mt][nt][1]);
            if (gr + 8 < nrows)
                H2[(gr + 8) * 64 + col2] = make_float2(acc[mt][nt][2], acc[mt][nt][3]);
        }
    }
}

// ---------------- aggregate + bias + L2 normalize + ReLU ----------------
// one warp/node; 8-deep index prefetch; __ldg gathers
template<int BF16OUT>
__global__ void agg_norm_relu_kernel(const float* __restrict__ bias,
                                     float4* __restrict__ OUText) {
    int node = (blockIdx.x * blockDim.x + threadIdx.x) >> 5;
    int lane = threadIdx.x & 31;
    if (node >= N_NODES) return;
    int s = g_off[node], e = g_off[node + 1];
    float4 acc = make_float4(0.f, 0.f, 0.f, 0.f);
    int i = s;
    for (; i + 7 < e; i += 8) {
        int u[8];
        #pragma unroll
        for (int j = 0; j < 8; j++) u[j] = __ldg(&g_srcs[i + j]);
        float4 v[8];
        #pragma unroll
        for (int j = 0; j < 8; j++) v[j] = __ldg(&g_h[u[j] * F4 + lane]);
        #pragma unroll
        for (int j = 0; j < 8; j++) {
            acc.x += v[j].x; acc.y += v[j].y; acc.z += v[j].z; acc.w += v[j].w;
        }
    }
    for (; i + 1 < e; i += 2) {
        int u0 = __ldg(&g_srcs[i]), u1 = __ldg(&g_srcs[i + 1]);
        float4 v0 = __ldg(&g_h[u0 * F4 + lane]);
        float4 v1 = __ldg(&g_h[u1 * F4 + lane]);
        acc.x += v0.x + v1.x; acc.y += v0.y + v1.y;
        acc.z += v0.z + v1.z; acc.w += v0.w + v1.w;
    }
    if (i < e) {
        float4 v = __ldg(&g_h[__ldg(&g_srcs[i]) * F4 + lane]);
        acc.x += v.x; acc.y += v.y; acc.z += v.z; acc.w += v.w;
    }
    float4 b4 = ((const float4*)bias)[lane];
    acc.x += b4.x; acc.y += b4.y; acc.z += b4.z; acc.w += b4.w;
    float ss = acc.x * acc.x + acc.y * acc.y + acc.z * acc.z + acc.w * acc.w;
    #pragma unroll
    for (int off = 16; off > 0; off >>= 1)
        ss += __shfl_xor_sync(0xFFFFFFFFu, ss, off);
    float inv = 1.f / fmaxf(sqrtf(ss), 1e-12f);
    float vals[4];
    vals[0] = fmaxf(acc.x * inv, 0.f);
    vals[1] = fmaxf(acc.y * inv, 0.f);
    vals[2] = fmaxf(acc.z * inv, 0.f);
    vals[3] = fmaxf(acc.w * inv, 0.f);
    if (BF16OUT) {
        __nv_bfloat16 hi[4], lo[4];
        #pragma unroll
        for (int j = 0; j < 4; j++) {
            hi[j] = __float2bfloat16(vals[j]);
            lo[j] = __float2bfloat16(vals[j] - __bfloat162float(hi[j]));
        }
        int idx = node * F + lane * 4;
        *(uint2*)&g_xhi[idx] = *(uint2*)hi;
        *(uint2*)&g_xlo[idx] = *(uint2*)lo;
    } else {
        OUText[node * F4 + lane] = make_float4(vals[0], vals[1], vals[2], vals[3]);
    }
}

// ---------------- final linear + softmax (128 nodes/block, pair-softmax) ----------------
#define HEAD_SMEM (128 * 128 * 4 + 128 * 40 * 4 + 40 * 4)

__global__ __launch_bounds__(256)
void final_kernel(const float4* __restrict__ X4,
                  const float4* __restrict__ Wl,
                  const float* __restrict__ bl,
                  float* __restrict__ logits,
                  float* __restrict__ probs) {
    extern __shared__ float sm_f[];
    float4* xsh4 = (float4*)sm_f;                    // [128][32]
    float4* wsh4 = (float4*)(sm_f + 128 * 128);      // [128][10]
    float*  blsh = sm_f + 128 * 128 + 128 * 40;      // [40]
    int tid = threadIdx.x;
    int n0 = blockIdx.x * 128;

    // load x rows (coalesced float4)
    for (int i = tid; i < 128 * 32; i += 256) {
        int n = i >> 5, c = i & 31;
        int gn = n0 + n;
        xsh4[i] = (gn < N_NODES) ? X4[gn * 32 + c] : make_float4(0.f, 0.f, 0.f, 0.f);
    }
    // load W (128x40 floats = 1280 float4)
    for (int i = tid; i < 1280; i += 256) wsh4[i] = Wl[i];
    if (tid < 40) blsh[tid] = bl[tid];
    __syncthreads();

    int node = tid >> 1;
    int half = tid & 1;           // classes half*20 .. half*20+19
    int gn = n0 + node;

    float acc[20];
    #pragma unroll
    for (int j = 0; j < 20; j++) acc[j] = blsh[half * 20 + j];

    const float4* xrow = xsh4 + node * 32;
    #pragma unroll 4
    for (int k4 = 0; k4 < 32; k4++) {
        float4 xv = xrow[k4];
        float xs[4] = {xv.x, xv.y, xv.z, xv.w};
        #pragma unroll
        for (int kk = 0; kk < 4; kk++) {
            int k = k4 * 4 + kk;
            const float4* wrow = wsh4 + k * 10 + half * 5;
            #pragma unroll
            for (int c4 = 0; c4 < 5; c4++) {
                float4 wv = wrow[c4];   // warp-broadcast
                acc[c4 * 4 + 0] += xs[kk] * wv.x;
                acc[c4 * 4 + 1] += xs[kk] * wv.y;
                acc[c4 * 4 + 2] += xs[kk] * wv.z;
                acc[c4 * 4 + 3] += xs[kk] * wv.w;
            }
        }
    }

    // pair softmax (lanes tid, tid^1 hold the two 20-class halves of one node)
    float m = -1e30f;
    #pragma unroll
    for (int j = 0; j < 20; j++) m = fmaxf(m, acc[j]);
    m = fmaxf(m, __shfl_xor_sync(0xFFFFFFFFu, m, 1));
    float sum = 0.f;
    float ex[20];
    #pragma unroll
    for (int j = 0; j < 20; j++) { ex[j] = expf(acc[j] - m); sum += ex[j]; }
    sum += __shfl_xor_sync(0xFFFFFFFFu, sum, 1);
    float inv = 1.f / sum;

    if (gn < N_NODES) {
        int base = gn * NCLASS + half * 20;
        #pragma unroll
        for (int j = 0; j < 20; j++) {
            logits[base + j] = acc[j];
            probs[base + j]  = ex[j] * inv;
        }
    }
}

// ---------------- launch ----------------
extern "C" void kernel_launch(void* const* d_in, const int* in_sizes, int n_in,
                              void* d_out, int out_size) {
    const float* x  = (const float*)d_in[0];
    const int*   ei = (const int*)d_in[1];
    const float* W1 = (const float*)d_in[2];
    const float* b1 = (const float*)d_in[3];
    const float* W2 = (const float*)d_in[4];
    const float* b2 = (const float*)d_in[5];
    const float* W3 = (const float*)d_in[6];
    const float* b3 = (const float*)d_in[7];
    const float* W4 = (const float*)d_in[8];
    const float* b4 = (const float*)d_in[9];
    const float* Wl = (const float*)d_in[10];
    const float* bl = (const float*)d_in[11];

    const int* src = ei;
    const int* dst = ei + N_EDGES;

    float* out    = (float*)d_out;
    float* logits = out;
    float* probs  = out + N_NODES * NCLASS;
    float* x4out  = out + 2 * N_NODES * NCLASS;

    const int T = 256;
    const int gemm_blocks = (N_NODES + 127) / 128;       // 391
    const int agg_blocks  = (N_NODES * 32 + T - 1) / T;  // 6250
    const int edge_blocks = (N_EDGES + T - 1) / T;       // 2500
    const int head_blocks = (N_NODES + 127) / 128;       // 391

    cudaFuncSetAttribute(gemm_mma_kernel, cudaFuncAttributeMaxDynamicSharedMemorySize, GEMM_SMEM);
    cudaFuncSetAttribute(final_kernel, cudaFuncAttributeMaxDynamicSharedMemorySize, HEAD_SMEM);

    // CSR build
    zero_cnt_kernel<<<(N_NODES + T - 1) / T, T>>>();
    hist_kernel<<<edge_blocks, T>>>(dst);
    scanA_kernel<<<SCAN_BLKS, 1024>>>();
    scanB_kernel<<<1, 64>>>();
    scanC_kernel<<<SCAN_BLKS, 1024>>>();
    fill_kernel<<<edge_blocks, T>>>(src, dst);

    // prep: x split + all W splits
    xsplit_kernel<<<(N_NODES * F4 + T - 1) / T, T>>>((const float4*)x);
    wprep_all_kernel<<<(4 * F * F + T - 1) / T, T>>>(W1, W2, W3, W4);

    // 4 layers
    gemm_mma_kernel<<<gemm_blocks, T, GEMM_SMEM>>>(0, N_NODES);
    agg_norm_relu_kernel<1><<<agg_blocks, T>>>(b1, nullptr);
    gemm_mma_kernel<<<gemm_blocks, T, GEMM_SMEM>>>(1, N_NODES);
    agg_norm_relu_kernel<1><<<agg_blocks, T>>>(b2, nullptr);
    gemm_mma_kernel<<<gemm_blocks, T, GEMM_SMEM>>>(2, N_NODES);
    agg_norm_relu_kernel<1><<<agg_blocks, T>>>(b3, nullptr);
    gemm_mma_kernel<<<gemm_blocks, T, GEMM_SMEM>>>(3, N_NODES);
    agg_norm_relu_kernel<0><<<agg_blocks, T>>>(b4, (float4*)x4out);

    // head
    final_kernel<<<head_blocks, T, HEAD_SMEM>>>((const float4*)x4out, (const float4*)Wl, bl, logits, probs);
}

// round 10
// speedup vs baseline: 1.7356x; 1.0368x over previous
#include <cuda_runtime.h>
#include <cuda_bf16.h>
#include <cstdint>
#include <math.h>

#define N_NODES 50000
#define N_EDGES 640000
#define F 128
#define F4 32
#define NCLASS 40
#define SCAN_BLKS 49

// ---------------- scratch (static __device__, no allocation) ----------------
__device__ float4        g_agg[N_NODES * F4];   // aggregated input sums (fp32)
__device__ float4        g_act[N_NODES * F4];   // layer activations (fp32)
__device__ __nv_bfloat16 g_wthi[4 * F * F];     // W^T hi, all 4 layers
__device__ __nv_bfloat16 g_wtlo[4 * F * F];     // W^T lo
__device__ int g_cnt[N_NODES];
__device__ int g_off[N_NODES + 1];
__device__ int g_cur[N_NODES];
__device__ int g_srcs[N_EDGES];
__device__ int g_bsum[64];
__device__ int g_bpre[64];

// ---------------- prep: zero counts + all 4 W -> Wt hi/lo bf16 ----------------
__global__ void prep_kernel(const float* __restrict__ W1,
                            const float* __restrict__ W2,
                            const float* __restrict__ W3,
                            const float* __restrict__ W4) {
    int i = blockIdx.x * blockDim.x + threadIdx.x;
    if (i < 4 * F * F) {
        int layer = i >> 14;
        int r = i & (F * F - 1);
        int k = r >> 7, n = r & 127;
        const float* W = (layer == 0) ? W1 : (layer == 1) ? W2 : (layer == 2) ? W3 : W4;
        float w = W[k * F + n];
        __nv_bfloat16 h = __float2bfloat16(w);
        g_wthi[layer * F * F + n * F + k] = h;
        g_wtlo[layer * F * F + n * F + k] = __float2bfloat16(w - __bfloat162float(h));
    }
    int z = i - 4 * F * F;
    if (z >= 0 && z < N_NODES) g_cnt[z] = 0;
}

// ---------------- CSR build ----------------
__global__ void hist_kernel(const int* __restrict__ dst) {
    int e = blockIdx.x * blockDim.x + threadIdx.x;
    if (e < N_EDGES) atomicAdd(&g_cnt[dst[e]], 1);
}

__global__ void scanA_kernel() {
    __shared__ int sh[1024];
    int tid = threadIdx.x;
    int i = blockIdx.x * 1024 + tid;
    int v = (i < N_NODES) ? g_cnt[i] : 0;
    sh[tid] = v;
    __syncthreads();
    for (int off = 1; off < 1024; off <<= 1) {
        int t = (tid >= off) ? sh[tid - off] : 0;
        __syncthreads();
        sh[tid] += t;
        __syncthreads();
    }
    if (i < N_NODES) g_off[i] = sh[tid] - v;
    if (tid == 1023) g_bsum[blockIdx.x] = sh[1023];
}

__global__ void scanB_kernel() {
    __shared__ int sh[64];
    int tid = threadIdx.x;
    int v = (tid < SCAN_BLKS) ? g_bsum[tid] : 0;
    sh[tid] = v;
    __syncthreads();
    for (int off = 1; off < 64; off <<= 1) {
        int t = (tid >= off) ? sh[tid - off] : 0;
        __syncthreads();
        sh[tid] += t;
        __syncthreads();
    }
    if (tid < SCAN_BLKS) g_bpre[tid] = sh[tid] - v;
    if (tid == 63) g_off[N_NODES] = sh[63];
}

__global__ void scanC_kernel() {
    int i = blockIdx.x * 1024 + threadIdx.x;
    if (i < N_NODES) {
        int o = g_off[i] + g_bpre[blockIdx.x];
        g_off[i] = o;
        g_cur[i] = o;
    }
}

__global__ void fill_kernel(const int* __restrict__ src,
                            const int* __restrict__ dst) {
    int e = blockIdx.x * blockDim.x + threadIdx.x;
    if (e < N_EDGES) {
        int d = dst[e];
        int p = atomicAdd(&g_cur[d], 1);
        g_srcs[p] = src[e];
    }
}

// ---------------- aggregate (pure sum, fp32 gather) ----------------
// SEL 0: gather from external x; SEL 1: gather from g_act. Writes g_agg.
template<int SEL>
__global__ void agg_sum_kernel(const float4* __restrict__ Xext) {
    int node = (blockIdx.x * blockDim.x + threadIdx.x) >> 5;
    int lane = threadIdx.x & 31;
    if (node >= N_NODES) return;
    int s = g_off[node], e = g_off[node + 1];
    const float4* tab = (SEL == 0) ? Xext : g_act;
    float4 acc = make_float4(0.f, 0.f, 0.f, 0.f);
    int i = s;
    for (; i + 7 < e; i += 8) {
        int u[8];
        #pragma unroll
        for (int j = 0; j < 8; j++) u[j] = __ldg(&g_srcs[i + j]);
        float4 v[8];
        #pragma unroll
        for (int j = 0; j < 8; j++) v[j] = __ldg(&tab[u[j] * F4 + lane]);
        #pragma unroll
        for (int j = 0; j < 8; j++) {
            acc.x += v[j].x; acc.y += v[j].y; acc.z += v[j].z; acc.w += v[j].w;
        }
    }
    for (; i + 1 < e; i += 2) {
        int u0 = __ldg(&g_srcs[i]), u1 = __ldg(&g_srcs[i + 1]);
        float4 v0 = __ldg(&tab[u0 * F4 + lane]);
        float4 v1 = __ldg(&tab[u1 * F4 + lane]);
        acc.x += v0.x + v1.x; acc.y += v0.y + v1.y;
        acc.z += v0.z + v1.z; acc.w += v0.w + v1.w;
    }
    if (i < e) {
        float4 v = __ldg(&tab[__ldg(&g_srcs[i]) * F4 + lane]);
        acc.x += v.x; acc.y += v.y; acc.z += v.z; acc.w += v.w;
    }
    g_agg[node * F4 + lane] = acc;
}

// ---------------- GEMM + bias + L2-normalize + ReLU (fused epilogue) ----------------
#define PT 40
#define GEMM_SMEM (4 * 128 * PT * 2 + 512 + 128 * 2 * 4)   // slabs + bias + ss

#define LDSM_X4(r0,r1,r2,r3,addr) \
    asm volatile("ldmatrix.sync.aligned.m8n8.x4.shared.b16 {%0,%1,%2,%3}, [%4];" \
        : "=r"(r0),"=r"(r1),"=r"(r2),"=r"(r3) : "r"(addr))
#define LDSM_X2(r0,r1,addr) \
    asm volatile("ldmatrix.sync.aligned.m8n8.x2.shared.b16 {%0,%1}, [%2];" \
        : "=r"(r0),"=r"(r1) : "r"(addr))
#define MMA16816(d,a0,a1,a2,a3,b0,b1) \
    asm volatile("mma.sync.aligned.m16n8k16.row.col.f32.bf16.bf16.f32 " \
        "{%0,%1,%2,%3},{%4,%5,%6,%7},{%8,%9},{%0,%1,%2,%3};" \
        : "+f"(d[0]),"+f"(d[1]),"+f"(d[2]),"+f"(d[3]) \
        : "r"(a0),"r"(a1),"r"(a2),"r"(a3),"r"(b0),"r"(b1))

__device__ __forceinline__ unsigned int smem_u32(const void* p) {
    return (unsigned int)__cvta_generic_to_shared(p);
}

// OUT 1: write g_act; OUT 0: write external (x4out)
template<int OUT>
__global__ __launch_bounds__(256, 2)
void gemm_norm_kernel(int layer, const float* __restrict__ bias,
                      float2* __restrict__ OUText, int nrows) {
    extern __shared__ __nv_bfloat16 sm_b[];
    __nv_bfloat16* xhi_s = sm_b;                  // [128][PT]
    __nv_bfloat16* xlo_s = xhi_s + 128 * PT;
    __nv_bfloat16* whi_s = xlo_s + 128 * PT;
    __nv_bfloat16* wlo_s = whi_s + 128 * PT;
    float* b_s  = (float*)(wlo_s + 128 * PT);     // [128]
    float* ss_s = b_s + 128;                      // [128][2]

    const int tid  = threadIdx.x;
    const int lane = tid & 31;
    const int w    = tid >> 5;
    const int wr   = (w & 3) * 32;
    const int wc   = (w >> 2) * 64;
    const int row0 = blockIdx.x * 128;
    const int woff = layer * (F * F / 8);

    if (tid < 128) b_s[tid] = bias[tid];

    float acc[2][8][4];
    #pragma unroll
    for (int mt = 0; mt < 2; mt++)
        #pragma unroll
        for (int nt = 0; nt < 8; nt++)
            #pragma unroll
            for (int j = 0; j < 4; j++) acc[mt][nt][j] = 0.f;

    const int l15 = lane & 15;
    const int koA = (lane >> 4) << 3;
    const int koB = (l15 >> 3) << 3;

    for (int ks = 0; ks < 4; ks++) {
        // X part: load agg fp32 + split to hi/lo (128 rows x 8 float4)
        #pragma unroll
        for (int i = tid; i < 1024; i += 256) {
            int r = i >> 3, c = i & 7;
            int gr = row0 + r;
            float4 v = make_float4(0.f, 0.f, 0.f, 0.f);
            if (gr < nrows) v = g_agg[gr * F4 + ks * 8 + c];
            float vals[4] = {v.x, v.y, v.z, v.w};
            __nv_bfloat16 hi[4], lo[4];
            #pragma unroll
            for (int j = 0; j < 4; j++) {
                hi[j] = __float2bfloat16(vals[j]);
                lo[j] = __float2bfloat16(vals[j] - __bfloat162float(hi[j]));
            }
            int off = r * PT + c * 4;
            *(uint2*)(xhi_s + off) = *(uint2*)hi;
            *(uint2*)(xlo_s + off) = *(uint2*)lo;
        }
        // W part: copy preconverted bf16 (2 x 128 rows x 4 uint4)
        #pragma unroll
        for (int i = tid; i < 1024; i += 256) {
            int whichW = i >> 9;
            int r = (i >> 2) & 127;
            int c = i & 3;
            int gidx = woff + r * 16 + ks * 4 + c;
            uint4 v = whichW ? ((const uint4*)g_wtlo)[gidx]
                             : ((const uint4*)g_wthi)[gidx];
            __nv_bfloat16* base = whichW ? wlo_s : whi_s;
            *(uint4*)(base + r * PT + c * 8) = v;
        }
        __syncthreads();

        #pragma unroll
        for (int j = 0; j < 2; j++) {
            unsigned int ahi[2][4], alo[2][4];
            #pragma unroll
            for (int mt = 0; mt < 2; mt++) {
                int r = wr + mt * 16 + l15;
                LDSM_X4(ahi[mt][0], ahi[mt][1], ahi[mt][2], ahi[mt][3],
                        smem_u32(xhi_s + r * PT + j * 16 + koA));
                LDSM_X4(alo[mt][0], alo[mt][1], alo[mt][2], alo[mt][3],
                        smem_u32(xlo_s + r * PT + j * 16 + koA));
            }
            #pragma unroll
            for (int nt = 0; nt < 8; nt++) {
                int boff = (wc + nt * 8 + (l15 & 7)) * PT + j * 16 + koB;
                unsigned int bh0, bh1, bl0, bl1;
                LDSM_X2(bh0, bh1, smem_u32(whi_s + boff));
                LDSM_X2(bl0, bl1, smem_u32(wlo_s + boff));
                #pragma unroll
                for (int mt = 0; mt < 2; mt++) {
                    MMA16816(acc[mt][nt], ahi[mt][0], ahi[mt][1], ahi[mt][2], ahi[mt][3], bh0, bh1);
                    MMA16816(acc[mt][nt], ahi[mt][0], ahi[mt][1], ahi[mt][2], ahi[mt][3], bl0, bl1);
                    MMA16816(acc[mt][nt], alo[mt][0], alo[mt][1], alo[mt][2], alo[mt][3], bh0, bh1);
                }
            }
        }
        __syncthreads();
    }

    // ---- epilogue: +bias, row L2-norm (cross warp-pair), ReLU, store ----
    const int rA = lane >> 2;
    const int cB = (lane & 3) * 2;
    float ssp[2][2];   // [mt][gr / gr+8]
    #pragma unroll
    for (int mt = 0; mt < 2; mt++) {
        ssp[mt][0] = 0.f; ssp[mt][1] = 0.f;
        #pragma unroll
        for (int nt = 0; nt < 8; nt++) {
            float b0 = b_s[wc + nt * 8 + cB];
            float b1 = b_s[wc + nt * 8 + cB + 1];
            acc[mt][nt][0] += b0; acc[mt][nt][1] += b1;
            acc[mt][nt][2] += b0; acc[mt][nt][3] += b1;
            ssp[mt][0] += acc[mt][nt][0] * acc[mt][nt][0] + acc[mt][nt][1] * acc[mt][nt][1];
            ssp[mt][1] += acc[mt][nt][2] * acc[mt][nt][2] + acc[mt][nt][3] * acc[mt][nt][3];
        }
        // reduce across the 4 lanes of the quad (same rows, different cols)
        #pragma unroll
        for (int d = 1; d < 4; d <<= 1) {
            ssp[mt][0] += __shfl_xor_sync(0xFFFFFFFFu, ssp[mt][0], d);
            ssp[mt][1] += __shfl_xor_sync(0xFFFFFFFFu, ssp[mt][1], d);
        }
        if ((lane & 3) == 0) {
            ss_s[(wr + mt * 16 + rA) * 2 + (w >> 2)]     = ssp[mt][0];
            ss_s[(wr + mt * 16 + rA + 8) * 2 + (w >> 2)] = ssp[mt][1];
        }
    }
    __syncthreads();

    #pragma unroll
    for (int mt = 0; mt < 2; mt++) {
        int r0l = wr + mt * 16 + rA;
        float ss0 = ss_s[r0l * 2] + ss_s[r0l * 2 + 1];
        float ss1 = ss_s[(r0l + 8) * 2] + ss_s[(r0l + 8) * 2 + 1];
        float inv0 = 1.f / fmaxf(sqrtf(ss0), 1e-12f);
        float inv1 = 1.f / fmaxf(sqrtf(ss1), 1e-12f);
        int gr = row0 + r0l;
        #pragma unroll
        for (int nt = 0; nt < 8; nt++) {
            int col2 = (wc + nt * 8 + cB) >> 1;
            float2 v0 = make_float2(fmaxf(acc[mt][nt][0] * inv0, 0.f),
                                    fmaxf(acc[mt][nt][1] * inv0, 0.f));
            float2 v1 = make_float2(fmaxf(acc[mt][nt][2] * inv1, 0.f),
                                    fmaxf(acc[mt][nt][3] * inv1, 0.f));
            if (OUT) {
                float2* A2 = (float2*)g_act;
                if (gr < nrows)     A2[gr * 64 + col2]       = v0;
                if (gr + 8 < nrows) A2[(gr + 8) * 64 + col2] = v1;
            } else {
                if (gr < nrows)     OUText[gr * 64 + col2]       = v0;
                if (gr + 8 < nrows) OUText[(gr + 8) * 64 + col2] = v1;
            }
        }
    }
}

// ---------------- final linear + softmax ----------------
#define HEAD_SMEM (128 * 128 * 4 + 128 * 40 * 4 + 40 * 4)

__global__ __launch_bounds__(256)
void final_kernel(const float4* __restrict__ X4,
                  const float4* __restrict__ Wl,
                  const float* __restrict__ bl,
                  float* __restrict__ logits,
                  float* __restrict__ probs) {
    extern __shared__ float sm_f[];
    float4* xsh4 = (float4*)sm_f;
    float4* wsh4 = (float4*)(sm_f + 128 * 128);
    float*  blsh = sm_f + 128 * 128 + 128 * 40;
    int tid = threadIdx.x;
    int n0 = blockIdx.x * 128;

    for (int i = tid; i < 128 * 32; i += 256) {
        int n = i >> 5, c = i & 31;
        int gn = n0 + n;
        xsh4[i] = (gn < N_NODES) ? X4[gn * 32 + c] : make_float4(0.f, 0.f, 0.f, 0.f);
    }
    for (int i = tid; i < 1280; i += 256) wsh4[i] = Wl[i];
    if (tid < 40) blsh[tid] = bl[tid];
    __syncthreads();

    int node = tid >> 1;
    int half = tid & 1;
    int gn = n0 + node;

    float acc[20];
    #pragma unroll
    for (int j = 0; j < 20; j++) acc[j] = blsh[half * 20 + j];

    const float4* xrow = xsh4 + node * 32;
    #pragma unroll 4
    for (int k4 = 0; k4 < 32; k4++) {
        float4 xv = xrow[k4];
        float xs[4] = {xv.x, xv.y, xv.z, xv.w};
        #pragma unroll
        for (int kk = 0; kk < 4; kk++) {
            int k = k4 * 4 + kk;
            const float4* wrow = wsh4 + k * 10 + half * 5;
            #pragma unroll
            for (int c4 = 0; c4 < 5; c4++) {
                float4 wv = wrow[c4];
                acc[c4 * 4 + 0] += xs[kk] * wv.x;
                acc[c4 * 4 + 1] += xs[kk] * wv.y;
                acc[c4 * 4 + 2] += xs[kk] * wv.z;
                acc[c4 * 4 + 3] += xs[kk] * wv.w;
            }
        }
    }

    float m = -1e30f;
    #pragma unroll
    for (int j = 0; j < 20; j++) m = fmaxf(m, acc[j]);
    m = fmaxf(m, __shfl_xor_sync(0xFFFFFFFFu, m, 1));
    float sum = 0.f;
    float ex[20];
    #pragma unroll
    for (int j = 0; j < 20; j++) { ex[j] = expf(acc[j] - m); sum += ex[j]; }
    sum += __shfl_xor_sync(0xFFFFFFFFu, sum, 1);
    float inv = 1.f / sum;

    if (gn < N_NODES) {
        int base = gn * NCLASS + half * 20;
        #pragma unroll
        for (int j = 0; j < 20; j++) {
            logits[base + j] = acc[j];
            probs[base + j]  = ex[j] * inv;
        }
    }
}

// ---------------- launch ----------------
extern "C" void kernel_launch(void* const* d_in, const int* in_sizes, int n_in,
                              void* d_out, int out_size) {
    const float* x  = (const float*)d_in[0];
    const int*   ei = (const int*)d_in[1];
    const float* W1 = (const float*)d_in[2];
    const float* b1 = (const float*)d_in[3];
    const float* W2 = (const float*)d_in[4];
    const float* b2 = (const float*)d_in[5];
    const float* W3 = (const float*)d_in[6];
    const float* b3 = (const float*)d_in[7];
    const float* W4 = (const float*)d_in[8];
    const float* b4 = (const float*)d_in[9];
    const float* Wl = (const float*)d_in[10];
    const float* bl = (const float*)d_in[11];

    const int* src = ei;
    const int* dst = ei + N_EDGES;

    float* out    = (float*)d_out;
    float* logits = out;
    float* probs  = out + N_NODES * NCLASS;
    float* x4out  = out + 2 * N_NODES * NCLASS;

    const int T = 256;
    const int gemm_blocks = (N_NODES + 127) / 128;
    const int agg_blocks  = (N_NODES * 32 + T - 1) / T;
    const int edge_blocks = (N_EDGES + T - 1) / T;
    const int head_blocks = (N_NODES + 127) / 128;
    const int prep_blocks = (4 * F * F + N_NODES + T - 1) / T;

    cudaFuncSetAttribute(gemm_norm_kernel<0>, cudaFuncAttributeMaxDynamicSharedMemorySize, GEMM_SMEM);
    cudaFuncSetAttribute(gemm_norm_kernel<1>, cudaFuncAttributeMaxDynamicSharedMemorySize, GEMM_SMEM);
    cudaFuncSetAttribute(final_kernel, cudaFuncAttributeMaxDynamicSharedMemorySize, HEAD_SMEM);

    // prep (zero counts + W splits) then CSR
    prep_kernel<<<prep_blocks, T>>>(W1, W2, W3, W4);
    hist_kernel<<<edge_blocks, T>>>(dst);
    scanA_kernel<<<SCAN_BLKS, 1024>>>();
    scanB_kernel<<<1, 64>>>();
    scanC_kernel<<<SCAN_BLKS, 1024>>>();
    fill_kernel<<<edge_blocks, T>>>(src, dst);

    // 4 layers: aggregate-then-GEMM (linearity of segment_sum)
    agg_sum_kernel<0><<<agg_blocks, T>>>((const float4*)x);
    gemm_norm_kernel<1><<<gemm_blocks, T, GEMM_SMEM>>>(0, b1, nullptr, N_NODES);
    agg_sum_kernel<1><<<agg_blocks, T>>>(nullptr);
    gemm_norm_kernel<1><<<gemm_blocks, T, GEMM_SMEM>>>(1, b2, nullptr, N_NODES);
    agg_sum_kernel<1><<<agg_blocks, T>>>(nullptr);
    gemm_norm_kernel<1><<<gemm_blocks, T, GEMM_SMEM>>>(2, b3, nullptr, N_NODES);
    agg_sum_kernel<1><<<agg_blocks, T>>>(nullptr);
    gemm_norm_kernel<0><<<gemm_blocks, T, GEMM_SMEM>>>(3, b4, (float2*)x4out, N_NODES);

    // head
    final_kernel<<<head_blocks, T, HEAD_SMEM>>>((const float4*)x4out, (const float4*)Wl, bl, logits, probs);
}